// round 1
// baseline (speedup 1.0000x reference)
#include <cuda_runtime.h>

// LightweightConv1d: x (B=8, T=4096, C=1024) fp32, weight (H=16, 1, K=7) fp32.
// y[b,t,c] = sum_k softmax(w[c%H])[k] * x[b, t+k-PAD, c]
//
// Strategy: thread = one float4 of channels (c4) x one T-chunk. Sliding
// 7-deep register window along T so each input float4 is read once per tile
// (+6 halo). Fully coalesced 16B accesses; pure HBM-streaming kernel.

#define CC   1024
#define HH   16
#define KK   7
#define PADP 3
#define TT   4096
#define BB   8
#define TCHUNK 32
#define C4   (CC / 4)   // 256 float4 groups -> blockDim.x

__global__ __launch_bounds__(C4) void lightconv_kernel(
    const float* __restrict__ x,
    const float* __restrict__ weight,
    float* __restrict__ out)
{
    const int c4 = threadIdx.x;                 // 0..255
    const int tiles_per_b = TT / TCHUNK;
    const int b  = blockIdx.x / tiles_per_b;
    const int t0 = (blockIdx.x % tiles_per_b) * TCHUNK;

    // --- per-thread softmax of the 4 head kernels this float4 uses ---
    // channels c4*4 .. c4*4+3 map to heads h0..h0+3 (4 | 16 so no wrap)
    const int h0 = (c4 * 4) % HH;
    float w[4][KK];
    #pragma unroll
    for (int j = 0; j < 4; j++) {
        const int h = h0 + j;
        float m = -1e30f;
        #pragma unroll
        for (int k = 0; k < KK; k++) {
            w[j][k] = weight[h * KK + k];
            m = fmaxf(m, w[j][k]);
        }
        float s = 0.0f;
        #pragma unroll
        for (int k = 0; k < KK; k++) {
            w[j][k] = expf(w[j][k] - m);
            s += w[j][k];
        }
        const float inv = 1.0f / s;
        #pragma unroll
        for (int k = 0; k < KK; k++) w[j][k] *= inv;
    }

    const float4* __restrict__ xv =
        reinterpret_cast<const float4*>(x) + (size_t)b * TT * C4 + c4;
    float4* __restrict__ ov =
        reinterpret_cast<float4*>(out) + (size_t)b * TT * C4 + c4;

    // --- sliding register window over T ---
    float4 win[KK];
    #pragma unroll
    for (int k = 0; k < KK - 1; k++) {
        const int t = t0 - PADP + k;
        win[k] = (t >= 0 && t < TT) ? xv[(size_t)t * C4]
                                    : make_float4(0.f, 0.f, 0.f, 0.f);
    }

    #pragma unroll
    for (int j = 0; j < TCHUNK; j++) {
        const int tl = t0 + j + PADP;           // newest element of window
        win[(j + KK - 1) % KK] =
            (tl < TT) ? xv[(size_t)tl * C4] : make_float4(0.f, 0.f, 0.f, 0.f);

        float4 acc = make_float4(0.f, 0.f, 0.f, 0.f);
        #pragma unroll
        for (int k = 0; k < KK; k++) {
            const float4 v = win[(j + k) % KK];
            acc.x = fmaf(w[0][k], v.x, acc.x);
            acc.y = fmaf(w[1][k], v.y, acc.y);
            acc.z = fmaf(w[2][k], v.z, acc.z);
            acc.w = fmaf(w[3][k], v.w, acc.w);
        }
        ov[(size_t)(t0 + j) * C4] = acc;
    }
}

extern "C" void kernel_launch(void* const* d_in, const int* in_sizes, int n_in,
                              void* d_out, int out_size)
{
    const float* x = (const float*)d_in[0];      // (B, T, C) fp32
    const float* weight = (const float*)d_in[1]; // (H, 1, K) fp32
    float* out = (float*)d_out;                  // (B, T, C) fp32

    const int grid = BB * (TT / TCHUNK);         // 1024 blocks
    lightconv_kernel<<<grid, C4>>>(x, weight, out);
}

// round 3
// speedup vs baseline: 1.0457x; 1.0457x over previous
#include <cuda_runtime.h>

// LightweightConv1d: x (B=8, T=4096, C=1024) fp32, weight (H=16,1,K=7) fp32.
// y[b,t,c] = sum_k softmax(w[c%H])[k] * x[b, t+k-3, c]
//
// Thread = one float4 of channels x a 64-long T strip. Outputs computed in
// groups of 8 with a 14-wide float4 register window: 8 independent LDG.128
// per group (MLP=8) so every warp keeps ~4KB of loads in flight -> HBM-bound
// at full rate even in the tail wave.

#define CC   1024
#define HH   16
#define KK   7
#define PADP 3
#define TT   4096
#define BB   8
#define TCHUNK 64
#define GRP    8
#define C4   (CC / 4)   // 256 float4 lanes per t -> blockDim.x

__global__ __launch_bounds__(C4, 2) void lightconv_kernel(
    const float* __restrict__ x,
    const float* __restrict__ weight,
    float* __restrict__ out)
{
    const int c4 = threadIdx.x;                 // 0..255
    const int tiles_per_b = TT / TCHUNK;        // 64
    const int b  = blockIdx.x / tiles_per_b;
    const int t0 = (blockIdx.x % tiles_per_b) * TCHUNK;

    // --- softmax of the 4 head kernels this float4 uses (heads h0..h0+3) ---
    const int h0 = (c4 * 4) % HH;
    float w0[KK], w1[KK], w2[KK], w3[KK];
    {
        float* wr[4] = {w0, w1, w2, w3};
        #pragma unroll
        for (int j = 0; j < 4; j++) {
            const int h = h0 + j;
            float m = -1e30f;
            #pragma unroll
            for (int k = 0; k < KK; k++) {
                wr[j][k] = weight[h * KK + k];
                m = fmaxf(m, wr[j][k]);
            }
            float s = 0.0f;
            #pragma unroll
            for (int k = 0; k < KK; k++) {
                wr[j][k] = __expf(wr[j][k] - m);
                s += wr[j][k];
            }
            const float inv = 1.0f / s;
            #pragma unroll
            for (int k = 0; k < KK; k++) wr[j][k] *= inv;
        }
    }

    const float4* __restrict__ xv =
        reinterpret_cast<const float4*>(x) + (size_t)b * TT * C4 + c4;
    float4* __restrict__ ov =
        reinterpret_cast<float4*>(out) + (size_t)b * TT * C4 + c4;

    const float4 z = make_float4(0.f, 0.f, 0.f, 0.f);

    // window: v[i] holds x[base - 3 + i]; v[0..5] carried, v[6..13] fresh
    float4 v[GRP + KK - 1];

    // prologue: v[0..5] = x[t0-3 .. t0+2]
    #pragma unroll
    for (int i = 0; i < KK - 1; i++) {
        const int t = t0 - PADP + i;
        v[i] = (t >= 0) ? xv[(size_t)t * C4] : z;   // t0+2 <= TT-62, no high bound
    }

    #pragma unroll 1
    for (int g = 0; g < TCHUNK / GRP; g++) {
        const int base = t0 + g * GRP;

        // 8 independent loads, issued together (MLP=8)
        #pragma unroll
        for (int i = 0; i < GRP; i++) {
            const int t = base + PADP + i;
            v[KK - 1 + i] = (t < TT) ? xv[(size_t)t * C4] : z;
        }

        #pragma unroll
        for (int j = 0; j < GRP; j++) {
            float4 acc = z;
            #pragma unroll
            for (int k = 0; k < KK; k++) {
                const float4 a = v[j + k];
                acc.x = fmaf(w0[k], a.x, acc.x);
                acc.y = fmaf(w1[k], a.y, acc.y);
                acc.z = fmaf(w2[k], a.z, acc.z);
                acc.w = fmaf(w3[k], a.w, acc.w);
            }
            ov[(size_t)(base + j) * C4] = acc;
        }

        // shift window tail
        #pragma unroll
        for (int i = 0; i < KK - 1; i++) v[i] = v[GRP + i];
    }
}

extern "C" void kernel_launch(void* const* d_in, const int* in_sizes, int n_in,
                              void* d_out, int out_size)
{
    const float* x = (const float*)d_in[0];      // (B, T, C) fp32
    const float* weight = (const float*)d_in[1]; // (H, 1, K) fp32
    float* out = (float*)d_out;                  // (B, T, C) fp32

    const int grid = BB * (TT / TCHUNK);         // 512 blocks
    lightconv_kernel<<<grid, C4>>>(x, weight, out);
}

// round 4
// speedup vs baseline: 1.0854x; 1.0380x over previous
#include <cuda_runtime.h>

// LightweightConv1d: x (B=8, T=4096, C=1024) fp32, weight (H=16,1,K=7) fp32.
// y[b,t,c] = sum_k softmax(w[c%H])[k] * x[b, t+k-3, c]
//
// Thread = one float4 of channels x a 128-long T strip (halo 4.7%).
// Outputs in groups of 8 with a 14-wide float4 register window: 8 independent
// LDG.128 per group (MLP=8). grid=256 <= single-wave capacity (2 blocks/SM x
// 148 SMs) -> no wave transition. Stores use .cs (evict-first) so the 128MB
// output stream doesn't evict input halo lines from L2.

#define CC   1024
#define HH   16
#define KK   7
#define PADP 3
#define TT   4096
#define BB   8
#define TCHUNK 128
#define GRP    8
#define C4   (CC / 4)   // 256 float4 lanes per t -> blockDim.x

__global__ __launch_bounds__(C4, 2) void lightconv_kernel(
    const float* __restrict__ x,
    const float* __restrict__ weight,
    float* __restrict__ out)
{
    const int c4 = threadIdx.x;                 // 0..255
    const int tiles_per_b = TT / TCHUNK;        // 32
    const int b  = blockIdx.x / tiles_per_b;
    const int t0 = (blockIdx.x % tiles_per_b) * TCHUNK;

    // --- softmax of the 4 head kernels this float4 uses (heads h0..h0+3) ---
    const int h0 = (c4 * 4) % HH;
    float w0[KK], w1[KK], w2[KK], w3[KK];
    {
        float* wr[4] = {w0, w1, w2, w3};
        #pragma unroll
        for (int j = 0; j < 4; j++) {
            const int h = h0 + j;
            float m = -1e30f;
            #pragma unroll
            for (int k = 0; k < KK; k++) {
                wr[j][k] = weight[h * KK + k];
                m = fmaxf(m, wr[j][k]);
            }
            float s = 0.0f;
            #pragma unroll
            for (int k = 0; k < KK; k++) {
                wr[j][k] = __expf(wr[j][k] - m);
                s += wr[j][k];
            }
            const float inv = 1.0f / s;
            #pragma unroll
            for (int k = 0; k < KK; k++) wr[j][k] *= inv;
        }
    }

    const float4* __restrict__ xv =
        reinterpret_cast<const float4*>(x) + (size_t)b * TT * C4 + c4;
    float4* __restrict__ ov =
        reinterpret_cast<float4*>(out) + (size_t)b * TT * C4 + c4;

    const float4 z = make_float4(0.f, 0.f, 0.f, 0.f);

    // window: v[i] holds x[base - 3 + i]; v[0..5] carried, v[6..13] fresh
    float4 v[GRP + KK - 1];

    // prologue: v[0..5] = x[t0-3 .. t0+2]
    #pragma unroll
    for (int i = 0; i < KK - 1; i++) {
        const int t = t0 - PADP + i;
        v[i] = (t >= 0) ? xv[(size_t)t * C4] : z;   // high bound safe: t0+2 <= TT-126
    }

    #pragma unroll 1
    for (int g = 0; g < TCHUNK / GRP; g++) {
        const int base = t0 + g * GRP;

        // 8 independent loads, issued together (MLP=8)
        #pragma unroll
        for (int i = 0; i < GRP; i++) {
            const int t = base + PADP + i;
            v[KK - 1 + i] = (t < TT) ? xv[(size_t)t * C4] : z;
        }

        #pragma unroll
        for (int j = 0; j < GRP; j++) {
            float4 acc = z;
            #pragma unroll
            for (int k = 0; k < KK; k++) {
                const float4 a = v[j + k];
                acc.x = fmaf(w0[k], a.x, acc.x);
                acc.y = fmaf(w1[k], a.y, acc.y);
                acc.z = fmaf(w2[k], a.z, acc.z);
                acc.w = fmaf(w3[k], a.w, acc.w);
            }
            // evict-first store: output is never re-read, keep L2 for input halo
            __stcs(&ov[(size_t)(base + j) * C4], acc);
        }

        // shift window tail
        #pragma unroll
        for (int i = 0; i < KK - 1; i++) v[i] = v[GRP + i];
    }
}

extern "C" void kernel_launch(void* const* d_in, const int* in_sizes, int n_in,
                              void* d_out, int out_size)
{
    const float* x = (const float*)d_in[0];      // (B, T, C) fp32
    const float* weight = (const float*)d_in[1]; // (H, 1, K) fp32
    float* out = (float*)d_out;                  // (B, T, C) fp32

    const int grid = BB * (TT / TCHUNK);         // 256 blocks -> single wave
    lightconv_kernel<<<grid, C4>>>(x, weight, out);
}